// round 14
// baseline (speedup 1.0000x reference)
#include <cuda_runtime.h>
#include <cstdint>

// ---------------- problem constants ----------------
#define B_    16
#define T_    2048
#define N_    24
#define C_    64
#define TAIL  25
#define PRED  24
#define EPS_  1e-5f
#define BN_   (B_*N_)             // 384
#define CNTF  ((float)(B_*N_*T_)) // 786432

typedef unsigned long long ull;

// ---------------- scratch ----------------
__device__ float g_gc  [(size_t)BN_*C_*T_];
__device__ float g_bufA[(size_t)BN_*C_*T_];
__device__ float g_bufB[(size_t)BN_*C_*T_];
__device__ float g_tail[BN_*C_*TAIL];
__device__ ull   g_Wp  [N_*N_*32];            // gc weights: slice n contiguous (768 ull)
__device__ ull   g_Wc  [4*6144];              // conv weights packed: [conv][((i*8+og)*3+dt)*4+q]
__device__ float g_sum[4][C_];
__device__ float g_sq [4][C_];

// ---------------- f32x2 helpers ----------------
__device__ __forceinline__ ull pk2(float lo, float hi) {
    ull r; asm("mov.b64 %0,{%1,%2};" : "=l"(r) : "f"(lo), "f"(hi)); return r;
}
__device__ __forceinline__ ull dup2(float v) {
    ull r; asm("mov.b64 %0,{%1,%1};" : "=l"(r) : "f"(v)); return r;
}
__device__ __forceinline__ void upk2(ull p, float& lo, float& hi) {
    asm("mov.b64 {%0,%1},%2;" : "=f"(lo), "=f"(hi) : "l"(p));
}
__device__ __forceinline__ void fma2(ull& d, ull a, ull b) {
    asm("fma.rn.f32x2 %0,%1,%2,%0;" : "+l"(d) : "l"(a), "l"(b));
}

// ---------------- kernel 1: Laplacian/Cheb/theta fold + zero BN stats ----------------
__global__ void k_prep(const float* __restrict__ adj, const float* __restrict__ theta) {
    __shared__ float sL[N_*N_], sT2[N_*N_], sdis[N_];
    int tx = threadIdx.x;
    if (tx < 4*C_) { ((float*)g_sum)[tx] = 0.f; ((float*)g_sq)[tx] = 0.f; }
    if (tx < N_) {
        float d = 0.f;
        for (int j = 0; j < N_; j++) d += adj[tx*N_ + j];
        sdis[tx] = (d > 0.f) ? rsqrtf(d) : 0.f;
    }
    __syncthreads();
    for (int p = tx; p < N_*N_; p += blockDim.x) {
        int i = p / N_, j = p % N_;
        sL[p] = sdis[i] * adj[j*N_ + i] * sdis[j];
    }
    __syncthreads();
    for (int p = tx; p < N_*N_; p += blockDim.x) {
        int i = p / N_, j = p % N_;
        float a = 0.f;
        for (int q = 0; q < N_; q++) a += sL[i*N_ + q] * sL[q*N_ + j];
        sT2[p] = 2.f*a - ((i == j) ? 1.f : 0.f);
    }
    __syncthreads();
    for (int e = tx; e < N_*N_*32; e += blockDim.x) {
        int op = e & 31, nm = e >> 5;
        int m = nm % N_, n = nm / N_;
        float p0 = (m == n) ? 1.f : 0.f;
        float p1 = sL[m*N_ + n];
        float p2 = sT2[m*N_ + n];
        int o0 = 2*op, o1 = o0 + 1;
        float lo = theta[o0]*p0 + theta[64 + o0]*p1 + theta[128 + o0]*p2;
        float hi = theta[o1]*p0 + theta[64 + o1]*p1 + theta[128 + o1]*p2;
        g_Wp[e] = pk2(lo, hi);
    }
}

// ---------------- kernel 1b: pack conv weights into paired layout ----------------
__global__ void k_packw(const float* __restrict__ w0, const float* __restrict__ w1,
                        const float* __restrict__ w2, const float* __restrict__ w3) {
    const float* w = (blockIdx.x == 0) ? w0 : (blockIdx.x == 1) ? w1
                   : (blockIdx.x == 2) ? w2 : w3;
    ull* dst = g_Wc + (size_t)blockIdx.x * 6144;
    for (int p = threadIdx.x; p < 6144; p += 256) {
        int q  = p & 3;
        int s  = p >> 2;
        int dt = s % 3;
        int g2 = s / 3;
        int og = g2 & 7;
        int i  = g2 >> 3;
        int c0 = (og*4 + q)*2;
        dst[p] = pk2(w[(c0*C_ + i)*3 + dt], w[((c0+1)*C_ + i)*3 + dt]);
    }
}

// ---------------- kernel 2: gc — split n across grid.z (4-way) for balance ----------------
#define GC_SMEM (2*768*8 + N_*128*4)    // 24576
__global__ void __launch_bounds__(256) k_gc(const float* __restrict__ x) {
    extern __shared__ char smraw[];
    ull*   sW = (ull*)smraw;                    // [2][768] double-buffered slice
    float* sx = (float*)(sW + 2*768);           // [m*128 + j]
    int tx = threadIdx.x;
    int t0 = blockIdx.x * 128;
    int b  = blockIdx.y;
    int n0 = blockIdx.z * 6;                    // this CTA: n in [n0, n0+6)

    const float* xb = x + ((size_t)b*T_ + t0) * N_;
    for (int p = tx; p < 128*N_; p += 256) {
        int j = p / N_, m = p % N_;
        sx[m*128 + j] = xb[p];
    }
    for (int p = tx; p < 768; p += 256) sW[p] = g_Wp[(size_t)n0*768 + p];
    __syncthreads();

    int l  = tx & 31;
    int og = tx >> 5;
    int jb = 4*l;

    for (int k = 0; k < 6; k++) {
        int n = n0 + k;
        const ull* cur = sW + (k & 1)*768;
        if (k + 1 < 6) {
            const ull* src = g_Wp + (size_t)(n + 1)*768;
            ull* dst = sW + ((k + 1) & 1)*768;
            for (int p = tx; p < 768; p += 256) dst[p] = src[p];
        }

        ull acc[4][4];
        #pragma unroll
        for (int q = 0; q < 4; q++)
            #pragma unroll
            for (int r = 0; r < 4; r++) acc[q][r] = 0ull;

        #pragma unroll 4
        for (int m = 0; m < N_; m++) {
            float4 Af = *(const float4*)&sx[m*128 + jb];
            ull dv[4];
            dv[0] = dup2(Af.x); dv[1] = dup2(Af.y);
            dv[2] = dup2(Af.z); dv[3] = dup2(Af.w);
            const ulonglong2* w2 = (const ulonglong2*)&cur[m*32 + og*4];
            ulonglong2 wa = w2[0], wb = w2[1];
            ull wr[4] = {wa.x, wa.y, wb.x, wb.y};
            #pragma unroll
            for (int r = 0; r < 4; r++) {
                ull vv = dv[r];
                #pragma unroll
                for (int q = 0; q < 4; q++) fma2(acc[q][r], wr[q], vv);
            }
        }
        int bn = b*N_ + n;
        #pragma unroll
        for (int q = 0; q < 4; q++) {
            int c0 = (og*4 + q)*2;
            float lo[4], hi[4];
            #pragma unroll
            for (int r = 0; r < 4; r++) upk2(acc[q][r], lo[r], hi[r]);
            float* q0 = &g_gc[((size_t)(bn*C_ + c0))*T_ + t0 + jb];
            *(float4*)q0        = make_float4(lo[0], lo[1], lo[2], lo[3]);
            *(float4*)(q0 + T_) = make_float4(hi[0], hi[1], hi[2], hi[3]);
        }
        __syncthreads();
    }
}

// ---------------- fused causal conv + BN stats ----------------
// Round-12 structure: plain float tile + dup2 in mainloop + 2x6KB smem weight
// chunks -> 46KB smem -> 4 CTAs/SM. il-loop unroll 4 to cut chunk-loop alu.
// MODE 0: input as-is; MODE 1: relu(bn(raw)); MODE 2: relu(relu(bn(raw)) + gc)
#define RLP_ 132
#define WCH  768                                // ull per 8-i weight chunk (6KB)
#define NCH  8                                  // chunks of 8 input channels
#define CONV_SMEM (2*WCH*8 + C_*RLP_*4)         // 12288 + 33792 = 46080
template<int DIL, int MODE, bool FULLSTORE>
__global__ void __launch_bounds__(256, 4) k_conv(
    const float* __restrict__ in,  const float* __restrict__ gc,
    const ull*   __restrict__ gW,  const float* __restrict__ bias,
    const float* __restrict__ pssum, const float* __restrict__ pssq,
    const float* __restrict__ pg,    const float* __restrict__ pbe,
    float* __restrict__ outF, float* __restrict__ outT,
    float* __restrict__ ssum, float* __restrict__ ssq)
{
    extern __shared__ char smraw[];
    ull*   swb = (ull*)smraw;                  // 2 weight chunk buffers
    float* sin = (float*)(swb + 2*WCH);        // [c*RLP_ + j]; sin[j] = x(t0-2*DIL+j)
    __shared__ float s_sc[C_], s_sh[C_];

    int tx = threadIdx.x;
    int t0 = blockIdx.x * 128;
    int bn = blockIdx.y;

    if (MODE != 0 && tx < C_) {
        float inv = 1.f / CNTF;
        float mu  = pssum[tx] * inv;
        float var = pssq[tx] * inv - mu*mu;
        float s   = pg[tx] * rsqrtf(var + EPS_);
        s_sc[tx] = s;
        s_sh[tx] = pbe[tx] - mu*s;
    }

    // prefetch weight chunk 0
    {
        const ulonglong2* src = (const ulonglong2*)gW;
        ulonglong2* dst = (ulonglong2*)swb;
        for (int p = tx; p < WCH/2; p += 256) dst[p] = src[p];
    }
    if (MODE != 0) __syncthreads();   // s_sc/s_sh ready for tile transform

    // input tile with causal halo + fused transform
    const float* inb = in + (size_t)bn*C_*T_;
    const float* gcb = (MODE == 2) ? gc + (size_t)bn*C_*T_ : nullptr;
    const int RL = 128 + 2*DIL;
    for (int p = tx; p < C_*RL; p += 256) {
        int c = p / RL, j = p % RL;
        int gt = t0 - 2*DIL + j;
        float v = 0.f;
        if (gt >= 0) {
            float r = inb[c*T_ + gt];
            if (MODE == 0) v = r;
            else {
                float h = fmaxf(0.f, s_sc[c]*r + s_sh[c]);
                v = (MODE == 1) ? h : fmaxf(0.f, h + gcb[c*T_ + gt]);
            }
        }
        sin[c*RLP_ + j] = v;
    }
    __syncthreads();

    int l  = tx & 31;        // lane owns t = t0 + 4*l + r
    int og = tx >> 5;        // warp owns 4 ch-pairs (8 channels)
    int jb = 4*l;

    ull acc[4][4];
    #pragma unroll
    for (int q = 0; q < 4; q++)
        #pragma unroll
        for (int r = 0; r < 4; r++) acc[q][r] = 0ull;

    const float* srow = sin + jb;
    const int NV = 4 + 2*DIL;

    for (int ch = 0; ch < NCH; ch++) {
        const ull* cur = swb + (ch & 1)*WCH + og*12;
        if (ch < NCH - 1) {
            const ulonglong2* src = (const ulonglong2*)(gW + (ch + 1)*WCH);
            ulonglong2* dst = (ulonglong2*)(swb + ((ch + 1) & 1)*WCH);
            for (int p = tx; p < WCH/2; p += 256) dst[p] = src[p];
        }

        #pragma unroll 4
        for (int il = 0; il < 8; il++) {
            int i = ch*8 + il;
            float4 Af = *(const float4*)(srow + i*RLP_);
            float4 Bf = *(const float4*)(srow + i*RLP_ + 4);
            float va[8] = {Af.x, Af.y, Af.z, Af.w, Bf.x, Bf.y, Bf.z, Bf.w};
            ull dv[8];
            #pragma unroll
            for (int k = 0; k < 8; k++) if (k < NV) dv[k] = dup2(va[k]);

            const ull* wp = cur + il*96;
            #pragma unroll
            for (int dt = 0; dt < 3; dt++) {
                const ulonglong2* w2 = (const ulonglong2*)(wp + dt*4);
                ulonglong2 wA = w2[0], wB = w2[1];
                ull wr[4] = {wA.x, wA.y, wB.x, wB.y};
                #pragma unroll
                for (int r = 0; r < 4; r++) {
                    ull vv = dv[r + dt*DIL];
                    #pragma unroll
                    for (int q = 0; q < 4; q++) fma2(acc[q][r], wr[q], vv);
                }
            }
        }
        __syncthreads();   // next chunk loaded; current buffer free for ch+2
    }

    // epilogue: bias, store (vectorized), per-channel stats
    float* outbF = FULLSTORE ? outF + (size_t)bn*C_*T_ : nullptr;
    int tb = t0 + jb;
    #pragma unroll
    for (int q = 0; q < 4; q++) {
        int c0 = (og*4 + q)*2, c1 = c0 + 1;
        float b0 = bias[c0], b1 = bias[c1];
        float lo[4], hi[4];
        #pragma unroll
        for (int r = 0; r < 4; r++) {
            upk2(acc[q][r], lo[r], hi[r]);
            lo[r] += b0; hi[r] += b1;
        }
        if (FULLSTORE) {
            *(float4*)&outbF[c0*T_ + tb] = make_float4(lo[0], lo[1], lo[2], lo[3]);
            *(float4*)&outbF[c1*T_ + tb] = make_float4(hi[0], hi[1], hi[2], hi[3]);
        } else {
            #pragma unroll
            for (int r = 0; r < 4; r++) {
                int ti = tb + r - (T_ - TAIL);
                if (ti >= 0) {
                    outT[(bn*C_ + c0)*TAIL + ti] = lo[r];
                    outT[(bn*C_ + c1)*TAIL + ti] = hi[r];
                }
            }
        }
        float sl  = lo[0]+lo[1]+lo[2]+lo[3];
        float sh2 = hi[0]+hi[1]+hi[2]+hi[3];
        float ql  = lo[0]*lo[0]+lo[1]*lo[1]+lo[2]*lo[2]+lo[3]*lo[3];
        float qh  = hi[0]*hi[0]+hi[1]*hi[1]+hi[2]*hi[2]+hi[3]*hi[3];
        #pragma unroll
        for (int off = 16; off; off >>= 1) {
            sl  += __shfl_xor_sync(0xffffffffu, sl,  off);
            sh2 += __shfl_xor_sync(0xffffffffu, sh2, off);
            ql  += __shfl_xor_sync(0xffffffffu, ql,  off);
            qh  += __shfl_xor_sync(0xffffffffu, qh,  off);
        }
        if (l == q) {
            atomicAdd(&ssum[c0], sl);  atomicAdd(&ssum[c1], sh2);
            atomicAdd(&ssq[c0],  ql);  atomicAdd(&ssq[c1],  qh);
        }
    }
}

// ---------------- head (inline BN finalize for stages 1 and 3) ----------------
__global__ void __launch_bounds__(64) k_head(
    const float* __restrict__ g1b, const float* __restrict__ be1b,
    const float* __restrict__ g2b, const float* __restrict__ be2b,
    const float* __restrict__ w_end, const float* __restrict__ b_end,
    const float* __restrict__ w_end1, const float* __restrict__ b_end1,
    float* __restrict__ out)
{
    __shared__ float s_out[C_*TAIL];
    __shared__ float s_e1[32*TAIL];
    int bn = blockIdx.x;
    int tx = threadIdx.x;
    int b = bn / N_, n = bn % N_;

    if (tx < C_) {
        int c = tx;
        float inv = 1.f / CNTF;
        float mu1  = g_sum[1][c]*inv, v1 = g_sq[1][c]*inv - mu1*mu1;
        float sc1  = g1b[c]*rsqrtf(v1 + EPS_), sh1 = be1b[c] - mu1*sc1;
        float mu3  = g_sum[3][c]*inv, v3 = g_sq[3][c]*inv - mu3*mu3;
        float sc3  = g2b[c]*rsqrtf(v3 + EPS_), sh3 = be2b[c] - mu3*sc3;
        size_t base = (size_t)(bn*C_ + c)*T_ + (T_ - TAIL);
        for (int ti = 0; ti < TAIL; ti++) {
            float r2 = g_bufB[base + ti];
            float h  = fmaxf(0.f, sc1*r2 + sh1);
            float o0 = fmaxf(0.f, h + g_gc[base + ti]);
            float r4 = g_tail[(bn*C_ + c)*TAIL + ti];
            float h4 = fmaxf(0.f, sc3*r4 + sh3);
            s_out[c*TAIL + ti] = h4 + o0;
        }
    }
    __syncthreads();
    if (tx < 32) {
        int oc = tx;
        for (int ti = 0; ti < TAIL; ti++) {
            float a = b_end[oc];
            for (int c = 0; c < C_; c++) a += w_end[oc*C_ + c] * s_out[c*TAIL + ti];
            s_e1[oc*TAIL + ti] = fmaxf(0.f, a);
        }
    }
    __syncthreads();
    if (tx < PRED) {
        int pr = tx;
        float a = b_end1[0];
        for (int oc = 0; oc < 32; oc++)
            a += w_end1[oc*2]   * s_e1[oc*TAIL + pr]
               + w_end1[oc*2+1] * s_e1[oc*TAIL + pr + 1];
        out[b*(PRED*N_) + pr*N_ + n] = a;
    }
}

// ---------------- launch ----------------
extern "C" void kernel_launch(void* const* d_in, const int* in_sizes, int n_in,
                              void* d_out, int out_size) {
    const float* batch_x = (const float*)d_in[0];
    const float* adj     = (const float*)d_in[1];
    const float* theta   = (const float*)d_in[2];
    const float* w1a = (const float*)d_in[3];  const float* b1a  = (const float*)d_in[4];
    const float* g1a = (const float*)d_in[5];  const float* be1a = (const float*)d_in[6];
    const float* w1b = (const float*)d_in[7];  const float* b1b  = (const float*)d_in[8];
    const float* g1b = (const float*)d_in[9];  const float* be1b = (const float*)d_in[10];
    const float* w2a = (const float*)d_in[11]; const float* b2a  = (const float*)d_in[12];
    const float* g2a = (const float*)d_in[13]; const float* be2a = (const float*)d_in[14];
    const float* w2b = (const float*)d_in[15]; const float* b2b  = (const float*)d_in[16];
    const float* g2b = (const float*)d_in[17]; const float* be2b = (const float*)d_in[18];
    const float* w_end  = (const float*)d_in[19]; const float* b_end  = (const float*)d_in[20];
    const float* w_end1 = (const float*)d_in[21]; const float* b_end1 = (const float*)d_in[22];
    float* out = (float*)d_out;

    void *p_gc_, *p_A_, *p_B_, *p_tail_, *p_sum_, *p_sq_, *p_Wc_;
    cudaGetSymbolAddress(&p_gc_,   g_gc);
    cudaGetSymbolAddress(&p_A_,    g_bufA);
    cudaGetSymbolAddress(&p_B_,    g_bufB);
    cudaGetSymbolAddress(&p_tail_, g_tail);
    cudaGetSymbolAddress(&p_sum_,  g_sum);
    cudaGetSymbolAddress(&p_sq_,   g_sq);
    cudaGetSymbolAddress(&p_Wc_,   g_Wc);
    float* p_gc   = (float*)p_gc_;
    float* p_A    = (float*)p_A_;
    float* p_B    = (float*)p_B_;
    float* p_tail = (float*)p_tail_;
    float* p_sum  = (float*)p_sum_;
    float* p_sq   = (float*)p_sq_;
    ull*   p_Wc   = (ull*)p_Wc_;

    cudaFuncSetAttribute(k_gc, cudaFuncAttributeMaxDynamicSharedMemorySize, GC_SMEM);
    cudaFuncSetAttribute(k_conv<1,0,true >, cudaFuncAttributeMaxDynamicSharedMemorySize, CONV_SMEM);
    cudaFuncSetAttribute(k_conv<1,1,true >, cudaFuncAttributeMaxDynamicSharedMemorySize, CONV_SMEM);
    cudaFuncSetAttribute(k_conv<2,2,true >, cudaFuncAttributeMaxDynamicSharedMemorySize, CONV_SMEM);
    cudaFuncSetAttribute(k_conv<2,1,false>, cudaFuncAttributeMaxDynamicSharedMemorySize, CONV_SMEM);

    dim3 cgrid(T_/128, BN_);

    k_prep<<<1, 256>>>(adj, theta);
    k_packw<<<4, 256>>>(w1a, w1b, w2a, w2b);
    k_gc<<<dim3(T_/128, B_, 4), 256, GC_SMEM>>>(batch_x);

    // conv1a: gc -> raw1(bufA), stats[0]
    k_conv<1,0,true ><<<cgrid, 256, CONV_SMEM>>>(p_gc, nullptr, p_Wc + 0*6144, b1a,
                                                 nullptr, nullptr, nullptr, nullptr,
                                                 p_A, nullptr, p_sum + 0*C_, p_sq + 0*C_);
    // conv1b: relu(bn0(raw1)) -> raw2(bufB), stats[1]
    k_conv<1,1,true ><<<cgrid, 256, CONV_SMEM>>>(p_A, nullptr, p_Wc + 1*6144, b1b,
                                                 p_sum + 0*C_, p_sq + 0*C_, g1a, be1a,
                                                 p_B, nullptr, p_sum + 1*C_, p_sq + 1*C_);
    // conv2a (dil2): out0 = relu(relu(bn1(raw2)) + gc) -> raw3(bufA), stats[2]
    k_conv<2,2,true ><<<cgrid, 256, CONV_SMEM>>>(p_B, p_gc, p_Wc + 2*6144, b2a,
                                                 p_sum + 1*C_, p_sq + 1*C_, g1b, be1b,
                                                 p_A, nullptr, p_sum + 2*C_, p_sq + 2*C_);
    // conv2b (dil2): relu(bn2(raw3)) -> tail only, stats[3]
    k_conv<2,1,false><<<cgrid, 256, CONV_SMEM>>>(p_A, nullptr, p_Wc + 3*6144, b2b,
                                                 p_sum + 2*C_, p_sq + 2*C_, g2a, be2a,
                                                 nullptr, p_tail, p_sum + 3*C_, p_sq + 3*C_);

    k_head<<<BN_, 64>>>(g1b, be1b, g2b, be2b, w_end, b_end, w_end1, b_end1, out);

    (void)in_sizes; (void)n_in; (void)out_size;
}

// round 15
// speedup vs baseline: 1.4821x; 1.4821x over previous
#include <cuda_runtime.h>
#include <cstdint>

// ---------------- problem constants ----------------
#define B_    16
#define T_    2048
#define N_    24
#define C_    64
#define TAIL  25
#define PRED  24
#define EPS_  1e-5f
#define BN_   (B_*N_)             // 384
#define CNTF  ((float)(B_*N_*T_)) // 786432

typedef unsigned long long ull;

// ---------------- scratch ----------------
__device__ float g_gc  [(size_t)BN_*C_*T_];
__device__ float g_bufA[(size_t)BN_*C_*T_];
__device__ float g_bufB[(size_t)BN_*C_*T_];
__device__ float g_tail[BN_*C_*TAIL];
__device__ ull   g_Wp  [N_*N_*32];            // gc weights: slice n contiguous (768 ull)
__device__ ull   g_Wc  [4*6144];              // conv weights packed: [conv][((i*8+og)*3+dt)*4+q]
__device__ float g_sum[4][C_];
__device__ float g_sq [4][C_];

// ---------------- f32x2 helpers ----------------
__device__ __forceinline__ ull pk2(float lo, float hi) {
    ull r; asm("mov.b64 %0,{%1,%2};" : "=l"(r) : "f"(lo), "f"(hi)); return r;
}
__device__ __forceinline__ ull dup2(float v) {
    ull r; asm("mov.b64 %0,{%1,%1};" : "=l"(r) : "f"(v)); return r;
}
__device__ __forceinline__ void upk2(ull p, float& lo, float& hi) {
    asm("mov.b64 {%0,%1},%2;" : "=f"(lo), "=f"(hi) : "l"(p));
}
__device__ __forceinline__ void fma2(ull& d, ull a, ull b) {
    asm("fma.rn.f32x2 %0,%1,%2,%0;" : "+l"(d) : "l"(a), "l"(b));
}

// ---------------- kernel 1: Laplacian/Cheb/theta fold + zero BN stats ----------------
__global__ void k_prep(const float* __restrict__ adj, const float* __restrict__ theta) {
    __shared__ float sL[N_*N_], sT2[N_*N_], sdis[N_];
    int tx = threadIdx.x;
    if (tx < 4*C_) { ((float*)g_sum)[tx] = 0.f; ((float*)g_sq)[tx] = 0.f; }
    if (tx < N_) {
        float d = 0.f;
        for (int j = 0; j < N_; j++) d += adj[tx*N_ + j];
        sdis[tx] = (d > 0.f) ? rsqrtf(d) : 0.f;
    }
    __syncthreads();
    for (int p = tx; p < N_*N_; p += blockDim.x) {
        int i = p / N_, j = p % N_;
        sL[p] = sdis[i] * adj[j*N_ + i] * sdis[j];
    }
    __syncthreads();
    for (int p = tx; p < N_*N_; p += blockDim.x) {
        int i = p / N_, j = p % N_;
        float a = 0.f;
        for (int q = 0; q < N_; q++) a += sL[i*N_ + q] * sL[q*N_ + j];
        sT2[p] = 2.f*a - ((i == j) ? 1.f : 0.f);
    }
    __syncthreads();
    for (int e = tx; e < N_*N_*32; e += blockDim.x) {
        int op = e & 31, nm = e >> 5;
        int m = nm % N_, n = nm / N_;
        float p0 = (m == n) ? 1.f : 0.f;
        float p1 = sL[m*N_ + n];
        float p2 = sT2[m*N_ + n];
        int o0 = 2*op, o1 = o0 + 1;
        float lo = theta[o0]*p0 + theta[64 + o0]*p1 + theta[128 + o0]*p2;
        float hi = theta[o1]*p0 + theta[64 + o1]*p1 + theta[128 + o1]*p2;
        g_Wp[e] = pk2(lo, hi);
    }
}

// ---------------- kernel 1b: pack conv weights into paired layout ----------------
__global__ void k_packw(const float* __restrict__ w0, const float* __restrict__ w1,
                        const float* __restrict__ w2, const float* __restrict__ w3) {
    const float* w = (blockIdx.x == 0) ? w0 : (blockIdx.x == 1) ? w1
                   : (blockIdx.x == 2) ? w2 : w3;
    ull* dst = g_Wc + (size_t)blockIdx.x * 6144;
    for (int p = threadIdx.x; p < 6144; p += 256) {
        int q  = p & 3;
        int s  = p >> 2;
        int dt = s % 3;
        int g2 = s / 3;
        int og = g2 & 7;
        int i  = g2 >> 3;
        int c0 = (og*4 + q)*2;
        dst[p] = pk2(w[(c0*C_ + i)*3 + dt], w[((c0+1)*C_ + i)*3 + dt]);
    }
}

// ---------------- kernel 2: gc — split n across grid.z for balance ----------------
#define GC_SMEM (2*768*8 + N_*128*4)    // 24576
__global__ void __launch_bounds__(256) k_gc(const float* __restrict__ x) {
    extern __shared__ char smraw[];
    ull*   sW = (ull*)smraw;                    // [2][768] double-buffered slice
    float* sx = (float*)(sW + 2*768);           // [m*128 + j]
    int tx = threadIdx.x;
    int t0 = blockIdx.x * 128;
    int b  = blockIdx.y;
    int n0 = blockIdx.z * 12;                   // this CTA: n in [n0, n0+12)

    const float* xb = x + ((size_t)b*T_ + t0) * N_;
    for (int p = tx; p < 128*N_; p += 256) {
        int j = p / N_, m = p % N_;
        sx[m*128 + j] = xb[p];
    }
    for (int p = tx; p < 768; p += 256) sW[p] = g_Wp[(size_t)n0*768 + p];
    __syncthreads();

    int l  = tx & 31;
    int og = tx >> 5;
    int jb = 4*l;

    for (int k = 0; k < 12; k++) {
        int n = n0 + k;
        const ull* cur = sW + (k & 1)*768;
        if (k + 1 < 12) {
            const ull* src = g_Wp + (size_t)(n + 1)*768;
            ull* dst = sW + ((k + 1) & 1)*768;
            for (int p = tx; p < 768; p += 256) dst[p] = src[p];
        }

        ull acc[4][4];
        #pragma unroll
        for (int q = 0; q < 4; q++)
            #pragma unroll
            for (int r = 0; r < 4; r++) acc[q][r] = 0ull;

        #pragma unroll 4
        for (int m = 0; m < N_; m++) {
            float4 Af = *(const float4*)&sx[m*128 + jb];
            ull dv[4];
            dv[0] = dup2(Af.x); dv[1] = dup2(Af.y);
            dv[2] = dup2(Af.z); dv[3] = dup2(Af.w);
            const ulonglong2* w2 = (const ulonglong2*)&cur[m*32 + og*4];
            ulonglong2 wa = w2[0], wb = w2[1];
            ull wr[4] = {wa.x, wa.y, wb.x, wb.y};
            #pragma unroll
            for (int r = 0; r < 4; r++) {
                ull vv = dv[r];
                #pragma unroll
                for (int q = 0; q < 4; q++) fma2(acc[q][r], wr[q], vv);
            }
        }
        int bn = b*N_ + n;
        #pragma unroll
        for (int q = 0; q < 4; q++) {
            int c0 = (og*4 + q)*2;
            float lo[4], hi[4];
            #pragma unroll
            for (int r = 0; r < 4; r++) upk2(acc[q][r], lo[r], hi[r]);
            float* q0 = &g_gc[((size_t)(bn*C_ + c0))*T_ + t0 + jb];
            *(float4*)q0        = make_float4(lo[0], lo[1], lo[2], lo[3]);
            *(float4*)(q0 + T_) = make_float4(hi[0], hi[1], hi[2], hi[3]);
        }
        __syncthreads();
    }
}

// ---------------- fused causal conv + BN stats ----------------
// Measured-best config (round 12): plain float tile + dup2 in mainloop +
// 2x6KB smem weight chunks -> 46KB smem -> 4 CTAs/SM, il-loop unroll 2.
// MODE 0: input as-is; MODE 1: relu(bn(raw)); MODE 2: relu(relu(bn(raw)) + gc)
#define RLP_ 132
#define WCH  768                                // ull per 8-i weight chunk (6KB)
#define NCH  8                                  // chunks of 8 input channels
#define CONV_SMEM (2*WCH*8 + C_*RLP_*4)         // 12288 + 33792 = 46080
template<int DIL, int MODE, bool FULLSTORE>
__global__ void __launch_bounds__(256, 4) k_conv(
    const float* __restrict__ in,  const float* __restrict__ gc,
    const ull*   __restrict__ gW,  const float* __restrict__ bias,
    const float* __restrict__ pssum, const float* __restrict__ pssq,
    const float* __restrict__ pg,    const float* __restrict__ pbe,
    float* __restrict__ outF, float* __restrict__ outT,
    float* __restrict__ ssum, float* __restrict__ ssq)
{
    extern __shared__ char smraw[];
    ull*   swb = (ull*)smraw;                  // 2 weight chunk buffers
    float* sin = (float*)(swb + 2*WCH);        // [c*RLP_ + j]; sin[j] = x(t0-2*DIL+j)
    __shared__ float s_sc[C_], s_sh[C_];

    int tx = threadIdx.x;
    int t0 = blockIdx.x * 128;
    int bn = blockIdx.y;

    if (MODE != 0 && tx < C_) {
        float inv = 1.f / CNTF;
        float mu  = pssum[tx] * inv;
        float var = pssq[tx] * inv - mu*mu;
        float s   = pg[tx] * rsqrtf(var + EPS_);
        s_sc[tx] = s;
        s_sh[tx] = pbe[tx] - mu*s;
    }

    // prefetch weight chunk 0
    {
        const ulonglong2* src = (const ulonglong2*)gW;
        ulonglong2* dst = (ulonglong2*)swb;
        for (int p = tx; p < WCH/2; p += 256) dst[p] = src[p];
    }
    if (MODE != 0) __syncthreads();   // s_sc/s_sh ready for tile transform

    // input tile with causal halo + fused transform
    const float* inb = in + (size_t)bn*C_*T_;
    const float* gcb = (MODE == 2) ? gc + (size_t)bn*C_*T_ : nullptr;
    const int RL = 128 + 2*DIL;
    for (int p = tx; p < C_*RL; p += 256) {
        int c = p / RL, j = p % RL;
        int gt = t0 - 2*DIL + j;
        float v = 0.f;
        if (gt >= 0) {
            float r = inb[c*T_ + gt];
            if (MODE == 0) v = r;
            else {
                float h = fmaxf(0.f, s_sc[c]*r + s_sh[c]);
                v = (MODE == 1) ? h : fmaxf(0.f, h + gcb[c*T_ + gt]);
            }
        }
        sin[c*RLP_ + j] = v;
    }
    __syncthreads();

    int l  = tx & 31;        // lane owns t = t0 + 4*l + r
    int og = tx >> 5;        // warp owns 4 ch-pairs (8 channels)
    int jb = 4*l;

    ull acc[4][4];
    #pragma unroll
    for (int q = 0; q < 4; q++)
        #pragma unroll
        for (int r = 0; r < 4; r++) acc[q][r] = 0ull;

    const float* srow = sin + jb;
    const int NV = 4 + 2*DIL;

    for (int ch = 0; ch < NCH; ch++) {
        const ull* cur = swb + (ch & 1)*WCH + og*12;
        if (ch < NCH - 1) {
            const ulonglong2* src = (const ulonglong2*)(gW + (ch + 1)*WCH);
            ulonglong2* dst = (ulonglong2*)(swb + ((ch + 1) & 1)*WCH);
            for (int p = tx; p < WCH/2; p += 256) dst[p] = src[p];
        }

        #pragma unroll 2
        for (int il = 0; il < 8; il++) {
            int i = ch*8 + il;
            float4 Af = *(const float4*)(srow + i*RLP_);
            float4 Bf = *(const float4*)(srow + i*RLP_ + 4);
            float va[8] = {Af.x, Af.y, Af.z, Af.w, Bf.x, Bf.y, Bf.z, Bf.w};
            ull dv[8];
            #pragma unroll
            for (int k = 0; k < 8; k++) if (k < NV) dv[k] = dup2(va[k]);

            const ull* wp = cur + il*96;
            #pragma unroll
            for (int dt = 0; dt < 3; dt++) {
                const ulonglong2* w2 = (const ulonglong2*)(wp + dt*4);
                ulonglong2 wA = w2[0], wB = w2[1];
                ull wr[4] = {wA.x, wA.y, wB.x, wB.y};
                #pragma unroll
                for (int r = 0; r < 4; r++) {
                    ull vv = dv[r + dt*DIL];
                    #pragma unroll
                    for (int q = 0; q < 4; q++) fma2(acc[q][r], wr[q], vv);
                }
            }
        }
        __syncthreads();   // next chunk loaded; current buffer free for ch+2
    }

    // epilogue: bias, store (vectorized), per-channel stats
    float* outbF = FULLSTORE ? outF + (size_t)bn*C_*T_ : nullptr;
    int tb = t0 + jb;
    #pragma unroll
    for (int q = 0; q < 4; q++) {
        int c0 = (og*4 + q)*2, c1 = c0 + 1;
        float b0 = bias[c0], b1 = bias[c1];
        float lo[4], hi[4];
        #pragma unroll
        for (int r = 0; r < 4; r++) {
            upk2(acc[q][r], lo[r], hi[r]);
            lo[r] += b0; hi[r] += b1;
        }
        if (FULLSTORE) {
            *(float4*)&outbF[c0*T_ + tb] = make_float4(lo[0], lo[1], lo[2], lo[3]);
            *(float4*)&outbF[c1*T_ + tb] = make_float4(hi[0], hi[1], hi[2], hi[3]);
        } else {
            #pragma unroll
            for (int r = 0; r < 4; r++) {
                int ti = tb + r - (T_ - TAIL);
                if (ti >= 0) {
                    outT[(bn*C_ + c0)*TAIL + ti] = lo[r];
                    outT[(bn*C_ + c1)*TAIL + ti] = hi[r];
                }
            }
        }
        float sl  = lo[0]+lo[1]+lo[2]+lo[3];
        float sh2 = hi[0]+hi[1]+hi[2]+hi[3];
        float ql  = lo[0]*lo[0]+lo[1]*lo[1]+lo[2]*lo[2]+lo[3]*lo[3];
        float qh  = hi[0]*hi[0]+hi[1]*hi[1]+hi[2]*hi[2]+hi[3]*hi[3];
        #pragma unroll
        for (int off = 16; off; off >>= 1) {
            sl  += __shfl_xor_sync(0xffffffffu, sl,  off);
            sh2 += __shfl_xor_sync(0xffffffffu, sh2, off);
            ql  += __shfl_xor_sync(0xffffffffu, ql,  off);
            qh  += __shfl_xor_sync(0xffffffffu, qh,  off);
        }
        if (l == q) {
            atomicAdd(&ssum[c0], sl);  atomicAdd(&ssum[c1], sh2);
            atomicAdd(&ssq[c0],  ql);  atomicAdd(&ssq[c1],  qh);
        }
    }
}

// ---------------- head (inline BN finalize for stages 1 and 3) ----------------
__global__ void __launch_bounds__(64) k_head(
    const float* __restrict__ g1b, const float* __restrict__ be1b,
    const float* __restrict__ g2b, const float* __restrict__ be2b,
    const float* __restrict__ w_end, const float* __restrict__ b_end,
    const float* __restrict__ w_end1, const float* __restrict__ b_end1,
    float* __restrict__ out)
{
    __shared__ float s_out[C_*TAIL];
    __shared__ float s_e1[32*TAIL];
    int bn = blockIdx.x;
    int tx = threadIdx.x;
    int b = bn / N_, n = bn % N_;

    if (tx < C_) {
        int c = tx;
        float inv = 1.f / CNTF;
        float mu1  = g_sum[1][c]*inv, v1 = g_sq[1][c]*inv - mu1*mu1;
        float sc1  = g1b[c]*rsqrtf(v1 + EPS_), sh1 = be1b[c] - mu1*sc1;
        float mu3  = g_sum[3][c]*inv, v3 = g_sq[3][c]*inv - mu3*mu3;
        float sc3  = g2b[c]*rsqrtf(v3 + EPS_), sh3 = be2b[c] - mu3*sc3;
        size_t base = (size_t)(bn*C_ + c)*T_ + (T_ - TAIL);
        for (int ti = 0; ti < TAIL; ti++) {
            float r2 = g_bufB[base + ti];
            float h  = fmaxf(0.f, sc1*r2 + sh1);
            float o0 = fmaxf(0.f, h + g_gc[base + ti]);
            float r4 = g_tail[(bn*C_ + c)*TAIL + ti];
            float h4 = fmaxf(0.f, sc3*r4 + sh3);
            s_out[c*TAIL + ti] = h4 + o0;
        }
    }
    __syncthreads();
    if (tx < 32) {
        int oc = tx;
        for (int ti = 0; ti < TAIL; ti++) {
            float a = b_end[oc];
            for (int c = 0; c < C_; c++) a += w_end[oc*C_ + c] * s_out[c*TAIL + ti];
            s_e1[oc*TAIL + ti] = fmaxf(0.f, a);
        }
    }
    __syncthreads();
    if (tx < PRED) {
        int pr = tx;
        float a = b_end1[0];
        for (int oc = 0; oc < 32; oc++)
            a += w_end1[oc*2]   * s_e1[oc*TAIL + pr]
               + w_end1[oc*2+1] * s_e1[oc*TAIL + pr + 1];
        out[b*(PRED*N_) + pr*N_ + n] = a;
    }
}

// ---------------- launch ----------------
extern "C" void kernel_launch(void* const* d_in, const int* in_sizes, int n_in,
                              void* d_out, int out_size) {
    const float* batch_x = (const float*)d_in[0];
    const float* adj     = (const float*)d_in[1];
    const float* theta   = (const float*)d_in[2];
    const float* w1a = (const float*)d_in[3];  const float* b1a  = (const float*)d_in[4];
    const float* g1a = (const float*)d_in[5];  const float* be1a = (const float*)d_in[6];
    const float* w1b = (const float*)d_in[7];  const float* b1b  = (const float*)d_in[8];
    const float* g1b = (const float*)d_in[9];  const float* be1b = (const float*)d_in[10];
    const float* w2a = (const float*)d_in[11]; const float* b2a  = (const float*)d_in[12];
    const float* g2a = (const float*)d_in[13]; const float* be2a = (const float*)d_in[14];
    const float* w2b = (const float*)d_in[15]; const float* b2b  = (const float*)d_in[16];
    const float* g2b = (const float*)d_in[17]; const float* be2b = (const float*)d_in[18];
    const float* w_end  = (const float*)d_in[19]; const float* b_end  = (const float*)d_in[20];
    const float* w_end1 = (const float*)d_in[21]; const float* b_end1 = (const float*)d_in[22];
    float* out = (float*)d_out;

    void *p_gc_, *p_A_, *p_B_, *p_tail_, *p_sum_, *p_sq_, *p_Wc_;
    cudaGetSymbolAddress(&p_gc_,   g_gc);
    cudaGetSymbolAddress(&p_A_,    g_bufA);
    cudaGetSymbolAddress(&p_B_,    g_bufB);
    cudaGetSymbolAddress(&p_tail_, g_tail);
    cudaGetSymbolAddress(&p_sum_,  g_sum);
    cudaGetSymbolAddress(&p_sq_,   g_sq);
    cudaGetSymbolAddress(&p_Wc_,   g_Wc);
    float* p_gc   = (float*)p_gc_;
    float* p_A    = (float*)p_A_;
    float* p_B    = (float*)p_B_;
    float* p_tail = (float*)p_tail_;
    float* p_sum  = (float*)p_sum_;
    float* p_sq   = (float*)p_sq_;
    ull*   p_Wc   = (ull*)p_Wc_;

    cudaFuncSetAttribute(k_gc, cudaFuncAttributeMaxDynamicSharedMemorySize, GC_SMEM);
    cudaFuncSetAttribute(k_conv<1,0,true >, cudaFuncAttributeMaxDynamicSharedMemorySize, CONV_SMEM);
    cudaFuncSetAttribute(k_conv<1,1,true >, cudaFuncAttributeMaxDynamicSharedMemorySize, CONV_SMEM);
    cudaFuncSetAttribute(k_conv<2,2,true >, cudaFuncAttributeMaxDynamicSharedMemorySize, CONV_SMEM);
    cudaFuncSetAttribute(k_conv<2,1,false>, cudaFuncAttributeMaxDynamicSharedMemorySize, CONV_SMEM);

    dim3 cgrid(T_/128, BN_);

    k_prep<<<1, 256>>>(adj, theta);
    k_packw<<<4, 256>>>(w1a, w1b, w2a, w2b);
    k_gc<<<dim3(T_/128, B_, 2), 256, GC_SMEM>>>(batch_x);

    // conv1a: gc -> raw1(bufA), stats[0]
    k_conv<1,0,true ><<<cgrid, 256, CONV_SMEM>>>(p_gc, nullptr, p_Wc + 0*6144, b1a,
                                                 nullptr, nullptr, nullptr, nullptr,
                                                 p_A, nullptr, p_sum + 0*C_, p_sq + 0*C_);
    // conv1b: relu(bn0(raw1)) -> raw2(bufB), stats[1]
    k_conv<1,1,true ><<<cgrid, 256, CONV_SMEM>>>(p_A, nullptr, p_Wc + 1*6144, b1b,
                                                 p_sum + 0*C_, p_sq + 0*C_, g1a, be1a,
                                                 p_B, nullptr, p_sum + 1*C_, p_sq + 1*C_);
    // conv2a (dil2): out0 = relu(relu(bn1(raw2)) + gc) -> raw3(bufA), stats[2]
    k_conv<2,2,true ><<<cgrid, 256, CONV_SMEM>>>(p_B, p_gc, p_Wc + 2*6144, b2a,
                                                 p_sum + 1*C_, p_sq + 1*C_, g1b, be1b,
                                                 p_A, nullptr, p_sum + 2*C_, p_sq + 2*C_);
    // conv2b (dil2): relu(bn2(raw3)) -> tail only, stats[3]
    k_conv<2,1,false><<<cgrid, 256, CONV_SMEM>>>(p_A, nullptr, p_Wc + 3*6144, b2b,
                                                 p_sum + 2*C_, p_sq + 2*C_, g2a, be2a,
                                                 nullptr, p_tail, p_sum + 3*C_, p_sq + 3*C_);

    k_head<<<BN_, 64>>>(g1b, be1b, g2b, be2b, w_end, b_end, w_end1, b_end1, out);

    (void)in_sizes; (void)n_in; (void)out_size;
}

// round 17
// speedup vs baseline: 1.5739x; 1.0620x over previous
#include <cuda_runtime.h>
#include <cstdint>

// ---------------- problem constants ----------------
#define B_    16
#define T_    2048
#define N_    24
#define C_    64
#define TAIL  25
#define PRED  24
#define EPS_  1e-5f
#define BN_   (B_*N_)             // 384
#define CNTF  ((float)(B_*N_*T_)) // 786432

typedef unsigned long long ull;

// ---------------- scratch ----------------
__device__ float g_gc  [(size_t)BN_*C_*T_];
__device__ float g_bufA[(size_t)BN_*C_*T_];
__device__ float g_bufB[(size_t)BN_*C_*T_];
__device__ float g_tail[BN_*C_*TAIL];
__device__ ull   g_Wp  [N_*N_*32];            // gc weights: slice n contiguous (768 ull)
__device__ ull   g_Wc  [4*6144];              // conv weights packed: [conv][((i*8+og)*3+dt)*4+q]
__device__ float g_sum[4][C_];
__device__ float g_sq [4][C_];

// ---------------- f32x2 helpers ----------------
__device__ __forceinline__ ull pk2(float lo, float hi) {
    ull r; asm("mov.b64 %0,{%1,%2};" : "=l"(r) : "f"(lo), "f"(hi)); return r;
}
__device__ __forceinline__ ull dup2(float v) {
    ull r; asm("mov.b64 %0,{%1,%1};" : "=l"(r) : "f"(v)); return r;
}
__device__ __forceinline__ void upk2(ull p, float& lo, float& hi) {
    asm("mov.b64 {%0,%1},%2;" : "=f"(lo), "=f"(hi) : "l"(p));
}
__device__ __forceinline__ void fma2(ull& d, ull a, ull b) {
    asm("fma.rn.f32x2 %0,%1,%2,%0;" : "+l"(d) : "l"(a), "l"(b));
}

// ---------------- kernel 1: Laplacian/Cheb/theta fold + zero BN stats ----------------
__global__ void k_prep(const float* __restrict__ adj, const float* __restrict__ theta) {
    __shared__ float sL[N_*N_], sT2[N_*N_], sdis[N_];
    int tx = threadIdx.x;
    if (tx < 4*C_) { ((float*)g_sum)[tx] = 0.f; ((float*)g_sq)[tx] = 0.f; }
    if (tx < N_) {
        float d = 0.f;
        for (int j = 0; j < N_; j++) d += adj[tx*N_ + j];
        sdis[tx] = (d > 0.f) ? rsqrtf(d) : 0.f;
    }
    __syncthreads();
    for (int p = tx; p < N_*N_; p += blockDim.x) {
        int i = p / N_, j = p % N_;
        sL[p] = sdis[i] * adj[j*N_ + i] * sdis[j];
    }
    __syncthreads();
    for (int p = tx; p < N_*N_; p += blockDim.x) {
        int i = p / N_, j = p % N_;
        float a = 0.f;
        for (int q = 0; q < N_; q++) a += sL[i*N_ + q] * sL[q*N_ + j];
        sT2[p] = 2.f*a - ((i == j) ? 1.f : 0.f);
    }
    __syncthreads();
    for (int e = tx; e < N_*N_*32; e += blockDim.x) {
        int op = e & 31, nm = e >> 5;
        int m = nm % N_, n = nm / N_;
        float p0 = (m == n) ? 1.f : 0.f;
        float p1 = sL[m*N_ + n];
        float p2 = sT2[m*N_ + n];
        int o0 = 2*op, o1 = o0 + 1;
        float lo = theta[o0]*p0 + theta[64 + o0]*p1 + theta[128 + o0]*p2;
        float hi = theta[o1]*p0 + theta[64 + o1]*p1 + theta[128 + o1]*p2;
        g_Wp[e] = pk2(lo, hi);
    }
}

// ---------------- kernel 1b: pack conv weights into paired layout ----------------
__global__ void k_packw(const float* __restrict__ w0, const float* __restrict__ w1,
                        const float* __restrict__ w2, const float* __restrict__ w3) {
    const float* w = (blockIdx.x == 0) ? w0 : (blockIdx.x == 1) ? w1
                   : (blockIdx.x == 2) ? w2 : w3;
    ull* dst = g_Wc + (size_t)blockIdx.x * 6144;
    for (int p = threadIdx.x; p < 6144; p += 256) {
        int q  = p & 3;
        int s  = p >> 2;
        int dt = s % 3;
        int g2 = s / 3;
        int og = g2 & 7;
        int i  = g2 >> 3;
        int c0 = (og*4 + q)*2;
        dst[p] = pk2(w[(c0*C_ + i)*3 + dt], w[((c0+1)*C_ + i)*3 + dt]);
    }
}

// ---------------- fused gc + conv1a kernel ----------------
// Phase 1: compute gc tile (64ch x 130t, 2-halo) for this bn into smem + gmem.
// Phase 2: champion conv mainloop (DIL=1, MODE 0) reading the smem tile.
// Smem aliasing: [region 18816B: phase1 x(12672)+gcW(6144) / phase2 chunks(12288)]
//                [tile 33792B].
#define RLP_ 132
#define WCH  768
#define NCH  8
#define GCONV_SMEM (18816 + C_*RLP_*4)          // 52608 -> 4 CTAs/SM
__global__ void __launch_bounds__(256, 4) k_gconv(
    const float* __restrict__ x,   const ull* __restrict__ gW,
    const float* __restrict__ bias,
    float* __restrict__ outF, float* __restrict__ ssum, float* __restrict__ ssq)
{
    extern __shared__ char smraw[];
    float* sx   = (float*)smraw;               // phase1: [m*132 + j], 24x132
    ull*   gcWs = (ull*)(smraw + 12672);       // phase1: 768 ull
    ull*   swb  = (ull*)smraw;                 // phase2: 2 weight chunks
    float* sin  = (float*)(smraw + 18816);     // gc tile [c*132 + j]; j=0 <-> t0-2

    int tx = threadIdx.x;
    int t0 = blockIdx.x * 128;
    int bn = blockIdx.y;
    int b  = bn / N_, n = bn % N_;
    int l  = tx & 31;
    int og = tx >> 5;

    // ---- phase 1: fill x tile + gc weights ----
    const float* xb = x + (size_t)b*T_*N_;
    for (int p = tx; p < N_*130; p += 256) {
        int j = p / N_, m = p % N_;
        int gt = t0 - 2 + j;
        sx[m*RLP_ + j] = (gt >= 0) ? xb[(size_t)gt*N_ + m] : 0.f;
    }
    for (int p = tx; p < 768; p += 256) gcWs[p] = g_Wp[(size_t)n*768 + p];
    __syncthreads();

    // gc compute: 8 warps x 4 ch-pairs; lane l covers j = l+32r (r<4) + tail j=128+l (l<2)
    {
        ull accg[4][4], acct[4];
        #pragma unroll
        for (int q = 0; q < 4; q++) {
            acct[q] = 0ull;
            #pragma unroll
            for (int r = 0; r < 4; r++) accg[q][r] = 0ull;
        }
        bool tl = (l < 2);
        for (int m = 0; m < N_; m++) {
            const ulonglong2* w2 = (const ulonglong2*)&gcWs[m*32 + og*4];
            ulonglong2 wa = w2[0], wb2 = w2[1];
            ull wr[4] = {wa.x, wa.y, wb2.x, wb2.y};
            const float* xr = sx + m*RLP_;
            #pragma unroll
            for (int r = 0; r < 4; r++) {
                ull vv = dup2(xr[l + 32*r]);
                #pragma unroll
                for (int q = 0; q < 4; q++) fma2(accg[q][r], wr[q], vv);
            }
            if (tl) {
                ull vv = dup2(xr[128 + l]);
                #pragma unroll
                for (int q = 0; q < 4; q++) fma2(acct[q], wr[q], vv);
            }
        }
        float* gcb = g_gc + (size_t)bn*C_*T_;
        #pragma unroll
        for (int q = 0; q < 4; q++) {
            int c0 = (og*4 + q)*2, c1 = c0 + 1;
            #pragma unroll
            for (int r = 0; r < 4; r++) {
                int j = l + 32*r;
                float lo, hi; upk2(accg[q][r], lo, hi);
                sin[c0*RLP_ + j] = lo;
                sin[c1*RLP_ + j] = hi;
                if (j >= 2) {
                    int t = t0 - 2 + j;
                    gcb[c0*T_ + t] = lo;
                    gcb[c1*T_ + t] = hi;
                }
            }
            if (tl) {
                int j = 128 + l;
                float lo, hi; upk2(acct[q], lo, hi);
                sin[c0*RLP_ + j] = lo;
                sin[c1*RLP_ + j] = hi;
                int t = t0 - 2 + j;
                gcb[c0*T_ + t] = lo;
                gcb[c1*T_ + t] = hi;
            }
        }
    }
    __syncthreads();   // x/gcW dead; tile complete

    // prefetch conv weight chunk 0 into (aliased) region
    {
        const ulonglong2* src = (const ulonglong2*)gW;
        ulonglong2* dst = (ulonglong2*)swb;
        for (int p = tx; p < WCH/2; p += 256) dst[p] = src[p];
    }
    __syncthreads();

    // ---- phase 2: champion conv mainloop (DIL=1) ----
    int jb = 4*l;
    ull acc[4][4];
    #pragma unroll
    for (int q = 0; q < 4; q++)
        #pragma unroll
        for (int r = 0; r < 4; r++) acc[q][r] = 0ull;

    const float* srow = sin + jb;
    const int NV = 6;

    for (int ch = 0; ch < NCH; ch++) {
        const ull* cur = swb + (ch & 1)*WCH + og*12;
        if (ch < NCH - 1) {
            const ulonglong2* src = (const ulonglong2*)(gW + (ch + 1)*WCH);
            ulonglong2* dst = (ulonglong2*)(swb + ((ch + 1) & 1)*WCH);
            for (int p = tx; p < WCH/2; p += 256) dst[p] = src[p];
        }
        #pragma unroll 2
        for (int il = 0; il < 8; il++) {
            int i = ch*8 + il;
            float4 Af = *(const float4*)(srow + i*RLP_);
            float4 Bf = *(const float4*)(srow + i*RLP_ + 4);
            float va[8] = {Af.x, Af.y, Af.z, Af.w, Bf.x, Bf.y, Bf.z, Bf.w};
            ull dv[8];
            #pragma unroll
            for (int k = 0; k < 8; k++) if (k < NV) dv[k] = dup2(va[k]);
            const ull* wp = cur + il*96;
            #pragma unroll
            for (int dt = 0; dt < 3; dt++) {
                const ulonglong2* w2 = (const ulonglong2*)(wp + dt*4);
                ulonglong2 wA = w2[0], wB = w2[1];
                ull wr[4] = {wA.x, wA.y, wB.x, wB.y};
                #pragma unroll
                for (int r = 0; r < 4; r++) {
                    ull vv = dv[r + dt];
                    #pragma unroll
                    for (int q = 0; q < 4; q++) fma2(acc[q][r], wr[q], vv);
                }
            }
        }
        __syncthreads();
    }

    // epilogue: bias, store, stats
    float* outbF = outF + (size_t)bn*C_*T_;
    int tb = t0 + jb;
    #pragma unroll
    for (int q = 0; q < 4; q++) {
        int c0 = (og*4 + q)*2, c1 = c0 + 1;
        float b0 = bias[c0], b1 = bias[c1];
        float lo[4], hi[4];
        #pragma unroll
        for (int r = 0; r < 4; r++) {
            upk2(acc[q][r], lo[r], hi[r]);
            lo[r] += b0; hi[r] += b1;
        }
        *(float4*)&outbF[c0*T_ + tb] = make_float4(lo[0], lo[1], lo[2], lo[3]);
        *(float4*)&outbF[c1*T_ + tb] = make_float4(hi[0], hi[1], hi[2], hi[3]);
        float sl  = lo[0]+lo[1]+lo[2]+lo[3];
        float sh2 = hi[0]+hi[1]+hi[2]+hi[3];
        float ql  = lo[0]*lo[0]+lo[1]*lo[1]+lo[2]*lo[2]+lo[3]*lo[3];
        float qh  = hi[0]*hi[0]+hi[1]*hi[1]+hi[2]*hi[2]+hi[3]*hi[3];
        #pragma unroll
        for (int off = 16; off; off >>= 1) {
            sl  += __shfl_xor_sync(0xffffffffu, sl,  off);
            sh2 += __shfl_xor_sync(0xffffffffu, sh2, off);
            ql  += __shfl_xor_sync(0xffffffffu, ql,  off);
            qh  += __shfl_xor_sync(0xffffffffu, qh,  off);
        }
        if (l == q) {
            atomicAdd(&ssum[c0], sl);  atomicAdd(&ssum[c1], sh2);
            atomicAdd(&ssq[c0],  ql);  atomicAdd(&ssq[c1],  qh);
        }
    }
}

// ---------------- fused causal conv + BN stats (champion config) ----------------
// MODE 1: relu(bn(raw)); MODE 2: relu(relu(bn(raw)) + gc)
#define CONV_SMEM (2*WCH*8 + C_*RLP_*4)         // 46080 -> 4 CTAs/SM
template<int DIL, int MODE, bool FULLSTORE>
__global__ void __launch_bounds__(256, 4) k_conv(
    const float* __restrict__ in,  const float* __restrict__ gc,
    const ull*   __restrict__ gW,  const float* __restrict__ bias,
    const float* __restrict__ pssum, const float* __restrict__ pssq,
    const float* __restrict__ pg,    const float* __restrict__ pbe,
    float* __restrict__ outF, float* __restrict__ outT,
    float* __restrict__ ssum, float* __restrict__ ssq)
{
    extern __shared__ char smraw[];
    ull*   swb = (ull*)smraw;
    float* sin = (float*)(swb + 2*WCH);
    __shared__ float s_sc[C_], s_sh[C_];

    int tx = threadIdx.x;
    int t0 = blockIdx.x * 128;
    int bn = blockIdx.y;

    if (tx < C_) {
        float inv = 1.f / CNTF;
        float mu  = pssum[tx] * inv;
        float var = pssq[tx] * inv - mu*mu;
        float s   = pg[tx] * rsqrtf(var + EPS_);
        s_sc[tx] = s;
        s_sh[tx] = pbe[tx] - mu*s;
    }

    {
        const ulonglong2* src = (const ulonglong2*)gW;
        ulonglong2* dst = (ulonglong2*)swb;
        for (int p = tx; p < WCH/2; p += 256) dst[p] = src[p];
    }
    __syncthreads();

    const float* inb = in + (size_t)bn*C_*T_;
    const float* gcb = (MODE == 2) ? gc + (size_t)bn*C_*T_ : nullptr;
    const int RL = 128 + 2*DIL;
    for (int p = tx; p < C_*RL; p += 256) {
        int c = p / RL, j = p % RL;
        int gt = t0 - 2*DIL + j;
        float v = 0.f;
        if (gt >= 0) {
            float r = inb[c*T_ + gt];
            float h = fmaxf(0.f, s_sc[c]*r + s_sh[c]);
            v = (MODE == 1) ? h : fmaxf(0.f, h + gcb[c*T_ + gt]);
        }
        sin[c*RLP_ + j] = v;
    }
    __syncthreads();

    int l  = tx & 31;
    int og = tx >> 5;
    int jb = 4*l;

    ull acc[4][4];
    #pragma unroll
    for (int q = 0; q < 4; q++)
        #pragma unroll
        for (int r = 0; r < 4; r++) acc[q][r] = 0ull;

    const float* srow = sin + jb;
    const int NV = 4 + 2*DIL;

    for (int ch = 0; ch < NCH; ch++) {
        const ull* cur = swb + (ch & 1)*WCH + og*12;
        if (ch < NCH - 1) {
            const ulonglong2* src = (const ulonglong2*)(gW + (ch + 1)*WCH);
            ulonglong2* dst = (ulonglong2*)(swb + ((ch + 1) & 1)*WCH);
            for (int p = tx; p < WCH/2; p += 256) dst[p] = src[p];
        }
        #pragma unroll 2
        for (int il = 0; il < 8; il++) {
            int i = ch*8 + il;
            float4 Af = *(const float4*)(srow + i*RLP_);
            float4 Bf = *(const float4*)(srow + i*RLP_ + 4);
            float va[8] = {Af.x, Af.y, Af.z, Af.w, Bf.x, Bf.y, Bf.z, Bf.w};
            ull dv[8];
            #pragma unroll
            for (int k = 0; k < 8; k++) if (k < NV) dv[k] = dup2(va[k]);
            const ull* wp = cur + il*96;
            #pragma unroll
            for (int dt = 0; dt < 3; dt++) {
                const ulonglong2* w2 = (const ulonglong2*)(wp + dt*4);
                ulonglong2 wA = w2[0], wB = w2[1];
                ull wr[4] = {wA.x, wA.y, wB.x, wB.y};
                #pragma unroll
                for (int r = 0; r < 4; r++) {
                    ull vv = dv[r + dt*DIL];
                    #pragma unroll
                    for (int q = 0; q < 4; q++) fma2(acc[q][r], wr[q], vv);
                }
            }
        }
        __syncthreads();
    }

    float* outbF = FULLSTORE ? outF + (size_t)bn*C_*T_ : nullptr;
    int tb = t0 + jb;
    #pragma unroll
    for (int q = 0; q < 4; q++) {
        int c0 = (og*4 + q)*2, c1 = c0 + 1;
        float b0 = bias[c0], b1 = bias[c1];
        float lo[4], hi[4];
        #pragma unroll
        for (int r = 0; r < 4; r++) {
            upk2(acc[q][r], lo[r], hi[r]);
            lo[r] += b0; hi[r] += b1;
        }
        if (FULLSTORE) {
            *(float4*)&outbF[c0*T_ + tb] = make_float4(lo[0], lo[1], lo[2], lo[3]);
            *(float4*)&outbF[c1*T_ + tb] = make_float4(hi[0], hi[1], hi[2], hi[3]);
        } else {
            #pragma unroll
            for (int r = 0; r < 4; r++) {
                int ti = tb + r - (T_ - TAIL);
                if (ti >= 0) {
                    outT[(bn*C_ + c0)*TAIL + ti] = lo[r];
                    outT[(bn*C_ + c1)*TAIL + ti] = hi[r];
                }
            }
        }
        float sl  = lo[0]+lo[1]+lo[2]+lo[3];
        float sh2 = hi[0]+hi[1]+hi[2]+hi[3];
        float ql  = lo[0]*lo[0]+lo[1]*lo[1]+lo[2]*lo[2]+lo[3]*lo[3];
        float qh  = hi[0]*hi[0]+hi[1]*hi[1]+hi[2]*hi[2]+hi[3]*hi[3];
        #pragma unroll
        for (int off = 16; off; off >>= 1) {
            sl  += __shfl_xor_sync(0xffffffffu, sl,  off);
            sh2 += __shfl_xor_sync(0xffffffffu, sh2, off);
            ql  += __shfl_xor_sync(0xffffffffu, ql,  off);
            qh  += __shfl_xor_sync(0xffffffffu, qh,  off);
        }
        if (l == q) {
            atomicAdd(&ssum[c0], sl);  atomicAdd(&ssum[c1], sh2);
            atomicAdd(&ssq[c0],  ql);  atomicAdd(&ssq[c1],  qh);
        }
    }
}

// ---------------- head (inline BN finalize for stages 1 and 3) ----------------
__global__ void __launch_bounds__(64) k_head(
    const float* __restrict__ g1b, const float* __restrict__ be1b,
    const float* __restrict__ g2b, const float* __restrict__ be2b,
    const float* __restrict__ w_end, const float* __restrict__ b_end,
    const float* __restrict__ w_end1, const float* __restrict__ b_end1,
    float* __restrict__ out)
{
    __shared__ float s_out[C_*TAIL];
    __shared__ float s_e1[32*TAIL];
    int bn = blockIdx.x;
    int tx = threadIdx.x;
    int b = bn / N_, n = bn % N_;

    if (tx < C_) {
        int c = tx;
        float inv = 1.f / CNTF;
        float mu1  = g_sum[1][c]*inv, v1 = g_sq[1][c]*inv - mu1*mu1;
        float sc1  = g1b[c]*rsqrtf(v1 + EPS_), sh1 = be1b[c] - mu1*sc1;
        float mu3  = g_sum[3][c]*inv, v3 = g_sq[3][c]*inv - mu3*mu3;
        float sc3  = g2b[c]*rsqrtf(v3 + EPS_), sh3 = be2b[c] - mu3*sc3;
        size_t base = (size_t)(bn*C_ + c)*T_ + (T_ - TAIL);
        for (int ti = 0; ti < TAIL; ti++) {
            float r2 = g_bufB[base + ti];
            float h  = fmaxf(0.f, sc1*r2 + sh1);
            float o0 = fmaxf(0.f, h + g_gc[base + ti]);
            float r4 = g_tail[(bn*C_ + c)*TAIL + ti];
            float h4 = fmaxf(0.f, sc3*r4 + sh3);
            s_out[c*TAIL + ti] = h4 + o0;
        }
    }
    __syncthreads();
    if (tx < 32) {
        int oc = tx;
        for (int ti = 0; ti < TAIL; ti++) {
            float a = b_end[oc];
            for (int c = 0; c < C_; c++) a += w_end[oc*C_ + c] * s_out[c*TAIL + ti];
            s_e1[oc*TAIL + ti] = fmaxf(0.f, a);
        }
    }
    __syncthreads();
    if (tx < PRED) {
        int pr = tx;
        float a = b_end1[0];
        for (int oc = 0; oc < 32; oc++)
            a += w_end1[oc*2]   * s_e1[oc*TAIL + pr]
               + w_end1[oc*2+1] * s_e1[oc*TAIL + pr + 1];
        out[b*(PRED*N_) + pr*N_ + n] = a;
    }
}

// ---------------- launch ----------------
extern "C" void kernel_launch(void* const* d_in, const int* in_sizes, int n_in,
                              void* d_out, int out_size) {
    const float* batch_x = (const float*)d_in[0];
    const float* adj     = (const float*)d_in[1];
    const float* theta   = (const float*)d_in[2];
    const float* w1a = (const float*)d_in[3];  const float* b1a  = (const float*)d_in[4];
    const float* g1a = (const float*)d_in[5];  const float* be1a = (const float*)d_in[6];
    const float* w1b = (const float*)d_in[7];  const float* b1b  = (const float*)d_in[8];
    const float* g1b = (const float*)d_in[9];  const float* be1b = (const float*)d_in[10];
    const float* w2a = (const float*)d_in[11]; const float* b2a  = (const float*)d_in[12];
    const float* g2a = (const float*)d_in[13]; const float* be2a = (const float*)d_in[14];
    const float* w2b = (const float*)d_in[15]; const float* b2b  = (const float*)d_in[16];
    const float* g2b = (const float*)d_in[17]; const float* be2b = (const float*)d_in[18];
    const float* w_end  = (const float*)d_in[19]; const float* b_end  = (const float*)d_in[20];
    const float* w_end1 = (const float*)d_in[21]; const float* b_end1 = (const float*)d_in[22];
    float* out = (float*)d_out;

    void *p_gc_, *p_A_, *p_B_, *p_tail_, *p_sum_, *p_sq_, *p_Wc_;
    cudaGetSymbolAddress(&p_gc_,   g_gc);
    cudaGetSymbolAddress(&p_A_,    g_bufA);
    cudaGetSymbolAddress(&p_B_,    g_bufB);
    cudaGetSymbolAddress(&p_tail_, g_tail);
    cudaGetSymbolAddress(&p_sum_,  g_sum);
    cudaGetSymbolAddress(&p_sq_,   g_sq);
    cudaGetSymbolAddress(&p_Wc_,   g_Wc);
    float* p_gc   = (float*)p_gc_;
    float* p_A    = (float*)p_A_;
    float* p_B    = (float*)p_B_;
    float* p_tail = (float*)p_tail_;
    float* p_sum  = (float*)p_sum_;
    float* p_sq   = (float*)p_sq_;
    ull*   p_Wc   = (ull*)p_Wc_;

    cudaFuncSetAttribute(k_gconv, cudaFuncAttributeMaxDynamicSharedMemorySize, GCONV_SMEM);
    cudaFuncSetAttribute(k_conv<1,1,true >, cudaFuncAttributeMaxDynamicSharedMemorySize, CONV_SMEM);
    cudaFuncSetAttribute(k_conv<2,2,true >, cudaFuncAttributeMaxDynamicSharedMemorySize, CONV_SMEM);
    cudaFuncSetAttribute(k_conv<2,1,false>, cudaFuncAttributeMaxDynamicSharedMemorySize, CONV_SMEM);

    dim3 cgrid(T_/128, BN_);

    k_prep<<<1, 256>>>(adj, theta);
    k_packw<<<4, 256>>>(w1a, w1b, w2a, w2b);

    // fused gc + conv1a: x -> gc(gmem) + raw1(bufA), stats[0]
    k_gconv<<<cgrid, 256, GCONV_SMEM>>>(batch_x, p_Wc + 0*6144, b1a,
                                        p_A, p_sum + 0*C_, p_sq + 0*C_);
    // conv1b: relu(bn0(raw1)) -> raw2(bufB), stats[1]
    k_conv<1,1,true ><<<cgrid, 256, CONV_SMEM>>>(p_A, nullptr, p_Wc + 1*6144, b1b,
                                                 p_sum + 0*C_, p_sq + 0*C_, g1a, be1a,
                                                 p_B, nullptr, p_sum + 1*C_, p_sq + 1*C_);
    // conv2a (dil2): out0 = relu(relu(bn1(raw2)) + gc) -> raw3(bufA), stats[2]
    k_conv<2,2,true ><<<cgrid, 256, CONV_SMEM>>>(p_B, p_gc, p_Wc + 2*6144, b2a,
                                                 p_sum + 1*C_, p_sq + 1*C_, g1b, be1b,
                                                 p_A, nullptr, p_sum + 2*C_, p_sq + 2*C_);
    // conv2b (dil2): relu(bn2(raw3)) -> tail only, stats[3]
    k_conv<2,1,false><<<cgrid, 256, CONV_SMEM>>>(p_A, nullptr, p_Wc + 3*6144, b2b,
                                                 p_sum + 2*C_, p_sq + 2*C_, g2a, be2a,
                                                 nullptr, p_tail, p_sum + 3*C_, p_sq + 3*C_);

    k_head<<<BN_, 64>>>(g1b, be1b, g2b, be2b, w_end, b_end, w_end1, b_end1, out);

    (void)in_sizes; (void)n_in; (void)out_size;
}